// round 2
// baseline (speedup 1.0000x reference)
#include <cuda_runtime.h>
#include <cstdint>
#include <cstddef>

// LISTA-CPSS: B=16384, M=256, N=1024, DEPTH=16
//   per iter: r = x - u @ A^T ; v = u + r @ W[i]^T ; u = shrinkss(v, t[i], p[i])
// shrinkss: per-row exact k-th-largest-of-|v| threshold (k = 1024 - idx),
//           mask = (|v|>=t && |v|>=thresh) -> pass-through else soft-threshold.

#define B_DIM  16384
#define M_DIM  256
#define N_DIM  1024
#define DEPTH  16

// Scratch (allocation-free: __device__ globals)
__device__ float g_r[(size_t)B_DIM * M_DIM];   // 16.7 MB
__device__ float g_v[(size_t)B_DIM * N_DIM];   // 67 MB

// ---------------------------------------------------------------------------
// Tiled SGEMM: C[i,j] = epilogue( sum_k X[i,k] * Y[j,k] )
//   X: [I,K] row-major (K contiguous), Y: [J,K] row-major (K contiguous)
//   MODE 0: C = bias - acc   (r = x - u A^T)
//   MODE 1: C = bias + acc   (v = u + r W^T)
//   MODE 2: C = acc          (iter 0: v = x W^T, u==0)
// Block tile 128x128, BK=8, 256 threads, 8x8 per thread.
// ---------------------------------------------------------------------------
template <int MODE>
__global__ __launch_bounds__(256, 2)
void gemm_nt(const float* __restrict__ X, const float* __restrict__ Y,
             const float* __restrict__ bias, float* __restrict__ C,
             int K, int ldc)
{
    __shared__ float sX[8][132];
    __shared__ float sY[8][132];

    const int bi  = blockIdx.x;   // row-block over B
    const int bj  = blockIdx.y;   // col-block over J
    const int tid = threadIdx.x;

    const int loadRow = tid >> 1;        // 0..127
    const int loadK4  = (tid & 1) * 4;   // 0 or 4

    const float* xg = X + (size_t)(bi * 128 + loadRow) * K + loadK4;
    const float* yg = Y + (size_t)(bj * 128 + loadRow) * K + loadK4;

    const int tx = tid & 15;   // 0..15 -> 8 cols each
    const int ty = tid >> 4;   // 0..15 -> 8 rows each

    float acc[8][8];
#pragma unroll
    for (int p = 0; p < 8; ++p)
#pragma unroll
        for (int q = 0; q < 8; ++q) acc[p][q] = 0.0f;

    for (int kt = 0; kt < K; kt += 8) {
        const float4 xv = *reinterpret_cast<const float4*>(xg + kt);
        const float4 yv = *reinterpret_cast<const float4*>(yg + kt);
        __syncthreads();
        sX[loadK4 + 0][loadRow] = xv.x;
        sX[loadK4 + 1][loadRow] = xv.y;
        sX[loadK4 + 2][loadRow] = xv.z;
        sX[loadK4 + 3][loadRow] = xv.w;
        sY[loadK4 + 0][loadRow] = yv.x;
        sY[loadK4 + 1][loadRow] = yv.y;
        sY[loadK4 + 2][loadRow] = yv.z;
        sY[loadK4 + 3][loadRow] = yv.w;
        __syncthreads();

#pragma unroll
        for (int k = 0; k < 8; ++k) {
            float a[8], b[8];
#pragma unroll
            for (int p = 0; p < 8; ++p) a[p] = sX[k][ty * 8 + p];
#pragma unroll
            for (int q = 0; q < 8; ++q) b[q] = sY[k][tx * 8 + q];
#pragma unroll
            for (int p = 0; p < 8; ++p)
#pragma unroll
                for (int q = 0; q < 8; ++q) acc[p][q] += a[p] * b[q];
        }
    }

    const int ci = bi * 128 + ty * 8;
    const int cj = bj * 128 + tx * 8;
#pragma unroll
    for (int p = 0; p < 8; ++p) {
        const size_t base = (size_t)(ci + p) * ldc + cj;
#pragma unroll
        for (int q0 = 0; q0 < 8; q0 += 4) {
            float4 o;
            float* po = reinterpret_cast<float*>(&o);
#pragma unroll
            for (int q = 0; q < 4; ++q) {
                float v = acc[p][q0 + q];
                if (MODE == 0)      v = bias[base + q0 + q] - v;
                else if (MODE == 1) v = bias[base + q0 + q] + v;
                po[q] = v;
            }
            *reinterpret_cast<float4*>(C + base + q0) = o;
        }
    }
}

// ---------------------------------------------------------------------------
// select_shrink: per row of V [1024], find thresh = k-th largest of |v|
// (bit-exact, via MSB-first 8-bit radix select on float bit pattern), then
//   u = mask ? v : sign(v)*max(|v|-t, 0),  mask = (|v|>=t && |v|>=thresh)
// One 256-thread block per row.
// ---------------------------------------------------------------------------
__global__ __launch_bounds__(256)
void select_shrink(const float* __restrict__ V, float* __restrict__ U,
                   const float* __restrict__ thr, int iter, int kth)
{
    __shared__ unsigned s_abs[1024];
    __shared__ unsigned s_hist[256];
    __shared__ unsigned s_scan[256];
    __shared__ unsigned s_sel[2];

    const int row = blockIdx.x;
    const int tid = threadIdx.x;

    const float4 vv = reinterpret_cast<const float4*>(V + (size_t)row * N_DIM)[tid];
    float va[4] = {vv.x, vv.y, vv.z, vv.w};
#pragma unroll
    for (int e = 0; e < 4; ++e)
        s_abs[e * 256 + tid] = __float_as_uint(fabsf(va[e]));
    // (order in s_abs is irrelevant: histogram only)

    unsigned prefix = 0, remaining = (unsigned)kth;

#pragma unroll 1
    for (int pass = 0; pass < 4; ++pass) {
        const int shift = 24 - pass * 8;
        const unsigned hmask = (pass == 0) ? 0u : (0xFFFFFFFFu << (shift + 8));

        s_hist[tid] = 0;
        __syncthreads();
#pragma unroll
        for (int e = 0; e < 4; ++e) {
            const unsigned b = s_abs[e * 256 + tid];
            if ((b & hmask) == prefix) atomicAdd(&s_hist[(b >> shift) & 255u], 1u);
        }
        __syncthreads();

        // suffix (reverse inclusive) scan over 256 bins
        s_scan[tid] = s_hist[tid];
        __syncthreads();
        for (int d = 1; d < 256; d <<= 1) {
            const unsigned add = (tid + d < 256) ? s_scan[tid + d] : 0u;
            __syncthreads();
            s_scan[tid] += add;
            __syncthreads();
        }
        // pick highest bin b with suffix(b) >= remaining
        const unsigned nxt = (tid < 255) ? s_scan[tid + 1] : 0u;
        if (s_scan[tid] >= remaining && nxt < remaining) {
            s_sel[0] = prefix | ((unsigned)tid << shift);
            s_sel[1] = remaining - nxt;
        }
        __syncthreads();
        prefix    = s_sel[0];
        remaining = s_sel[1];
        __syncthreads();
    }

    const float th = __uint_as_float(prefix);  // exact sorted_asc[idx]
    const float t  = thr[iter];

    float4 ov;
    float* po = reinterpret_cast<float*>(&ov);
#pragma unroll
    for (int e = 0; e < 4; ++e) {
        const float x = va[e];
        const float a = fabsf(x);
        po[e] = (a >= t && a >= th) ? x : copysignf(fmaxf(a - t, 0.0f), x);
    }
    reinterpret_cast<float4*>(U + (size_t)row * N_DIM)[tid] = ov;
}

// ---------------------------------------------------------------------------
// Host launcher: 16 iterations, iter 0 special-cased (u == 0, d_out poisoned).
// Graph-capturable: kernel launches only.
// ---------------------------------------------------------------------------
extern "C" void kernel_launch(void* const* d_in, const int* in_sizes, int n_in,
                              void* d_out, int out_size)
{
    const float* x   = (const float*)d_in[0];   // [B, M]
    const float* A   = (const float*)d_in[1];   // [M, N]
    const float* W   = (const float*)d_in[2];   // [DEPTH, N, M]
    const float* thr = (const float*)d_in[3];   // [DEPTH]
    float* u = (float*)d_out;                   // [B, N]

    float *rp, *vp;
    cudaGetSymbolAddress((void**)&rp, g_r);
    cudaGetSymbolAddress((void**)&vp, g_v);

    // idx_i = ceil((100 - p_i)/100 * 1024) - 1, p_i = min((i+1)*1.2, 5)
    // kth_i = 1024 - idx_i
    static const int KTH[DEPTH] = {13, 25, 37, 50, 52, 52, 52, 52,
                                   52, 52, 52, 52, 52, 52, 52, 52};

    const dim3 blk(256);
    const dim3 g1(B_DIM / 128, M_DIM / 128);   // (128, 2)
    const dim3 g2(B_DIM / 128, N_DIM / 128);   // (128, 8)

    // ---- iteration 0: u = 0  =>  r = x, v = x @ W0^T ----
    gemm_nt<2><<<g2, blk>>>(x, W, nullptr, vp, M_DIM, N_DIM);
    select_shrink<<<B_DIM, blk>>>(vp, u, thr, 0, KTH[0]);

    // ---- iterations 1..15 ----
    for (int i = 1; i < DEPTH; ++i) {
        // r = x - u @ A^T
        gemm_nt<0><<<g1, blk>>>(u, A, x, rp, N_DIM, M_DIM);
        // v = u + r @ W[i]^T
        gemm_nt<1><<<g2, blk>>>(rp, W + (size_t)i * N_DIM * M_DIM, u, vp,
                                M_DIM, N_DIM);
        // u = shrinkss(v)
        select_shrink<<<B_DIM, blk>>>(vp, u, thr, i, KTH[i]);
    }
}